// round 15
// baseline (speedup 1.0000x reference)
#include <cuda_runtime.h>
#include <cuda_fp16.h>
#include <cstdint>

#define B_  256
#define T_  512
#define I_  24
#define H_  128
#define G_  512           // 4*H
#define BT_ (B_*T_)       // 131072
#define MB_ 8             // batch rows per scan block
#define HAS_ 136          // hA row stride in halves (128 + 8 pad)
#define SAS_ 40           // GEMM smem row stride in halves (32 + 8 pad)
#define XS_  40           // x smem row stride in halves
#define YBS_ 132          // ybuf row stride in floats (128 + 4 pad)

static const size_t Y1SZ_ = (size_t)BT_ * 2 * H_;   // 33,554,432
#define GEMM_SMEM (8 * 128 * SAS_ * 2)              // 4 bufs x (A+W) = 81920 B

// ---------------- scratch (no cudaMalloc allowed) ----------------
// gx layout: [t][bg(32)][j(512)][bp(8)] fp32.
__device__ float  g_gx[2][(size_t)BT_ * G_];        // layer-1 gx
__device__ __half g_y0h[(size_t)BT_ * 2 * H_];      // 64 MB, rows r' = t*B + b
__device__ __half g_xh[(size_t)BT_ * 32];           // x padded 24->32, rows r' = t*B + b
__device__ __half g_w1h[2][G_ * 256];               // w_ih layer1, fp16

__device__ __forceinline__ float tanhap(float x) {
    float y; asm("tanh.approx.f32 %0, %1;" : "=f"(y) : "f"(x)); return y;
}
__device__ __forceinline__ void cp16(unsigned dst, const void* src) {
    asm volatile("cp.async.ca.shared.global [%0], [%1], 16;" :: "r"(dst), "l"(src));
}

// ---------------- conversion kernels ----------------
__global__ void conv_x_kernel(const float* __restrict__ x) {
    int idx = blockIdx.x * 256 + threadIdx.x;
    if (idx < BT_ * 32) {
        int r = idx >> 5, i = idx & 31;       // r' = t*256 + b
        int b = r & 255, t = r >> 8;
        g_xh[idx] = (i < I_) ? __float2half(x[((size_t)b * T_ + t) * I_ + i]) : __float2half(0.f);
    }
}

__global__ void conv_w1_kernel(const float* __restrict__ w1f, const float* __restrict__ w1b) {
    int idx = blockIdx.x * 256 + threadIdx.x;
    if (idx < 2 * G_ * 256) {
        int d = idx / (G_ * 256); int p = idx % (G_ * 256);
        const float* w = d ? w1b : w1f;
        g_w1h[d][p] = __float2half(w[p]);
    }
}

// ---------------- pipelined input GEMM (layer 1): 4-buffer depth-3 pipeline ----
__global__ __launch_bounds__(256) void gemm_gx_kernel(
    const float* __restrict__ biasf, const float* __restrict__ biasb)
{
    const int K = 256;
    extern __shared__ __half smem_dyn[];
    __half* sA = smem_dyn;                    // 4 bufs x 128*SAS_
    __half* sW = smem_dyn + 4 * 128 * SAS_;

    const int dir = blockIdx.x >> 2;
    const __half* __restrict__ A = g_y0h;
    const __half* __restrict__ W = g_w1h[dir];
    const float* __restrict__ bias = dir ? biasb : biasf;
    float* __restrict__ gx = g_gx[dir];

    const int tid  = threadIdx.x;
    const int lane = tid & 31;
    const int warp = tid >> 5;
    const int warpM = warp & 3;
    const int warpN = warp >> 2;
    const int g4 = lane >> 2;
    const int tg = lane & 3;
    const int mblk = blockIdx.y * 128;
    const int nblk = (blockIdx.x & 3) * 128;

    const unsigned sA_base = (unsigned)__cvta_generic_to_shared(sA);
    const unsigned sW_base = (unsigned)__cvta_generic_to_shared(sW);

    const int lrow = tid >> 2;
    const int lseg = tid & 3;

    auto load_stage = [&](int ks, int buf) {
        #pragma unroll
        for (int rr = 0; rr < 2; rr++) {
            int r = lrow + rr * 64;
            const __half* srcA = A + (size_t)(mblk + r) * K + ks * 32 + lseg * 8;
            const __half* srcW = W + (size_t)(nblk + r) * K + ks * 32 + lseg * 8;
            unsigned off = (unsigned)(buf * 128 * SAS_ + r * SAS_ + lseg * 8) * 2;
            cp16(sA_base + off, srcA);
            cp16(sW_base + off, srcW);
        }
        asm volatile("cp.async.commit_group;");
    };

    float acc[2][8][4];
    #pragma unroll
    for (int mf = 0; mf < 2; mf++)
        #pragma unroll
        for (int nf = 0; nf < 8; nf++)
            #pragma unroll
            for (int q = 0; q < 4; q++) acc[mf][nf][q] = 0.f;

    load_stage(0, 0);
    load_stage(1, 1);
    load_stage(2, 2);

    const unsigned lmA0 = sA_base + ((warpM * 32 + (lane & 15)) * SAS_ + (lane >> 4) * 8) * 2;
    const unsigned lmW0 = sW_base + ((warpN * 64 + ((lane >> 4) & 1) * 8 + (lane & 7)) * SAS_
                                     + ((lane >> 3) & 1) * 8) * 2;

    #pragma unroll
    for (int ks = 0; ks < 8; ks++) {
        if (ks < 6)       { asm volatile("cp.async.wait_group 2;"); }
        else if (ks == 6) { asm volatile("cp.async.wait_group 1;"); }
        else              { asm volatile("cp.async.wait_group 0;"); }
        __syncthreads();
        if (ks + 3 < 8) load_stage(ks + 3, (ks + 3) & 3);

        const int buf = ks & 3;
        const unsigned aBuf = lmA0 + buf * 128 * SAS_ * 2;
        const unsigned wBuf = lmW0 + buf * 128 * SAS_ * 2;

        #pragma unroll
        for (int kk = 0; kk < 2; kk++) {
            unsigned a[2][4];
            #pragma unroll
            for (int mf = 0; mf < 2; mf++) {
                asm volatile("ldmatrix.sync.aligned.m8n8.x4.shared.b16 {%0,%1,%2,%3}, [%4];"
                    : "=r"(a[mf][0]), "=r"(a[mf][1]), "=r"(a[mf][2]), "=r"(a[mf][3])
                    : "r"(aBuf + (mf * 16 * SAS_ + kk * 16) * 2));
            }
            #pragma unroll
            for (int nf2 = 0; nf2 < 4; nf2++) {
                unsigned b0, b1, b2, b3;
                asm volatile("ldmatrix.sync.aligned.m8n8.x4.shared.b16 {%0,%1,%2,%3}, [%4];"
                    : "=r"(b0), "=r"(b1), "=r"(b2), "=r"(b3)
                    : "r"(wBuf + (nf2 * 16 * SAS_ + kk * 16) * 2));
                #pragma unroll
                for (int mf = 0; mf < 2; mf++) {
                    asm volatile(
                        "mma.sync.aligned.m16n8k16.row.col.f32.f16.f16.f32 "
                        "{%0,%1,%2,%3}, {%4,%5,%6,%7}, {%8,%9}, {%0,%1,%2,%3};"
                        : "+f"(acc[mf][2*nf2][0]), "+f"(acc[mf][2*nf2][1]),
                          "+f"(acc[mf][2*nf2][2]), "+f"(acc[mf][2*nf2][3])
                        : "r"(a[mf][0]), "r"(a[mf][1]), "r"(a[mf][2]), "r"(a[mf][3]),
                          "r"(b0), "r"(b1));
                    asm volatile(
                        "mma.sync.aligned.m16n8k16.row.col.f32.f16.f16.f32 "
                        "{%0,%1,%2,%3}, {%4,%5,%6,%7}, {%8,%9}, {%0,%1,%2,%3};"
                        : "+f"(acc[mf][2*nf2+1][0]), "+f"(acc[mf][2*nf2+1][1]),
                          "+f"(acc[mf][2*nf2+1][2]), "+f"(acc[mf][2*nf2+1][3])
                        : "r"(a[mf][0]), "r"(a[mf][1]), "r"(a[mf][2]), "r"(a[mf][3]),
                          "r"(b2), "r"(b3));
                }
            }
        }
    }

    // epilogue -> gx[t][bg][j][bp]
    const int t = mblk >> 8;
    const int bbase = mblk & 255;
    #pragma unroll
    for (int mf = 0; mf < 2; mf++) {
        int b1 = bbase + warpM * 32 + mf * 16 + g4;
        int b2 = b1 + 8;
        #pragma unroll
        for (int nf = 0; nf < 8; nf++) {
            int n0 = nblk + warpN * 64 + nf * 8 + tg * 2;
            float sc = ((n0 >> 7) == 2) ? 1.f : 0.5f;
            float bv0 = bias[n0], bv1 = bias[n0 + 1];
            size_t o1 = (((size_t)t * 32 + (b1 >> 3)) * G_ + n0) * 8 + g4;
            gx[o1]     = sc * (acc[mf][nf][0] + bv0);
            gx[o1 + 8] = sc * (acc[mf][nf][1] + bv1);
            size_t o2 = (((size_t)t * 32 + (b2 >> 3)) * G_ + n0) * 8 + g4;
            gx[o2]     = sc * (acc[mf][nf][2] + bv0);
            gx[o2 + 8] = sc * (acc[mf][nf][3] + bv1);
        }
    }
}

// ---------------- layer-0 FUSED scan; split accumulation chains ----------------
__global__ __launch_bounds__(512) void lstm_scan_fused0(
    const float* __restrict__ wihf, const float* __restrict__ whhf, const float* __restrict__ bf_,
    const float* __restrict__ wihb, const float* __restrict__ whhb, const float* __restrict__ bb_,
    float* __restrict__ hn, float* __restrict__ cn)
{
    __shared__ __half hA[2 * 8 * HAS_];
    __shared__ __half xS[2 * 8 * XS_];

    const int tid  = threadIdx.x;
    const int lane = tid & 31;
    const int w    = tid >> 5;
    const int dir  = blockIdx.y;
    const int b0   = blockIdx.x * MB_;
    const int g4 = lane >> 2, tg = lane & 3;
    const float* __restrict__ whh  = dir ? whhb : whhf;
    const float* __restrict__ wih  = dir ? wihb : wihf;
    const float* __restrict__ bias = dir ? bb_ : bf_;

    unsigned Af[8][2][4];
    #pragma unroll
    for (int ks = 0; ks < 8; ks++)
        #pragma unroll
        for (int tl = 0; tl < 2; tl++) {
            const float* pA = whh + (size_t)((2 * tl)     * 128 + 8 * w + g4) * H_ + ks * 16 + tg * 2;
            const float* pB = whh + (size_t)((2 * tl + 1) * 128 + 8 * w + g4) * H_ + ks * 16 + tg * 2;
            float scA = (tl == 0) ? 0.5f : 1.0f;
            float scB = 0.5f;
            float2 vA0 = *(const float2*)pA;
            float2 vB0 = *(const float2*)pB;
            float2 vA1 = *(const float2*)(pA + 8);
            float2 vB1 = *(const float2*)(pB + 8);
            __half2 h0 = __floats2half2_rn(scA * vA0.x, scA * vA0.y);
            __half2 h1 = __floats2half2_rn(scB * vB0.x, scB * vB0.y);
            __half2 h2 = __floats2half2_rn(scA * vA1.x, scA * vA1.y);
            __half2 h3 = __floats2half2_rn(scB * vB1.x, scB * vB1.y);
            Af[ks][tl][0] = *(unsigned*)&h0;
            Af[ks][tl][1] = *(unsigned*)&h1;
            Af[ks][tl][2] = *(unsigned*)&h2;
            Af[ks][tl][3] = *(unsigned*)&h3;
        }

    unsigned Ax[2][2][4];
    #pragma unroll
    for (int ks = 0; ks < 2; ks++)
        #pragma unroll
        for (int tl = 0; tl < 2; tl++) {
            int rA = (2 * tl) * 128 + 8 * w + g4;
            int rB = (2 * tl + 1) * 128 + 8 * w + g4;
            float scA = (tl == 0) ? 0.5f : 1.0f;
            float scB = 0.5f;
            int k0 = ks * 16 + tg * 2;
            int k1 = k0 + 8;
            float2 vA0 = *(const float2*)(wih + (size_t)rA * I_ + k0);
            float2 vB0 = *(const float2*)(wih + (size_t)rB * I_ + k0);
            float2 vA1 = (k1 < I_) ? *(const float2*)(wih + (size_t)rA * I_ + k1) : make_float2(0.f, 0.f);
            float2 vB1 = (k1 < I_) ? *(const float2*)(wih + (size_t)rB * I_ + k1) : make_float2(0.f, 0.f);
            __half2 h0 = __floats2half2_rn(scA * vA0.x, scA * vA0.y);
            __half2 h1 = __floats2half2_rn(scB * vB0.x, scB * vB0.y);
            __half2 h2 = __floats2half2_rn(scA * vA1.x, scA * vA1.y);
            __half2 h3 = __floats2half2_rn(scB * vB1.x, scB * vB1.y);
            Ax[ks][tl][0] = *(unsigned*)&h0;
            Ax[ks][tl][1] = *(unsigned*)&h1;
            Ax[ks][tl][2] = *(unsigned*)&h2;
            Ax[ks][tl][3] = *(unsigned*)&h3;
        }

    const int hc = 8 * w + g4;
    const float bi = 0.5f * bias[hc];
    const float bfv = 0.5f * bias[128 + hc];
    const float bg  = bias[256 + hc];
    const float bo  = 0.5f * bias[384 + hc];

    for (int p = tid; p < 2 * 8 * HAS_; p += 512) hA[p] = __float2half(0.f);

    const int brow0 = b0 + 2 * tg;
    const int brow1 = brow0 + 1;
    float cst0 = 0.f, cst1 = 0.f;
    float h0v = 0.f, h1v = 0.f;

    const unsigned hA_base = (unsigned)__cvta_generic_to_shared(hA);
    const unsigned xS_base = (unsigned)__cvta_generic_to_shared(xS);
    const unsigned lmB4 = hA_base + (((lane & 7) * HAS_) + ((lane >> 3) & 3) * 8) * 2;
    const unsigned lmX4 = xS_base + (((lane & 7) * XS_)  + ((lane >> 3) & 3) * 8) * 2;
    const unsigned BUFB = 8 * HAS_ * 2;
    const unsigned XBUF = 8 * XS_ * 2;

    const int yr = tid >> 6;
    const int yc = (tid & 63) * 2;

    {
        int t0 = dir ? (T_ - 1) : 0;
        if (tid < 32) {
            int row = tid >> 2, seg = tid & 3;
            cp16(xS_base + (unsigned)(row * XS_ + seg * 8) * 2,
                 g_xh + ((size_t)t0 * B_ + b0 + row) * 32 + seg * 8);
            asm volatile("cp.async.commit_group;");
            asm volatile("cp.async.wait_group 0;");
        }
    }
    __syncthreads();

    for (int s = 0; s < T_; s++) {
        const int rb = s & 1;
        const unsigned lm = lmB4 + rb * BUFB;
        const unsigned lx = lmX4 + rb * XBUF;
        __half* hw = hA + (rb ^ 1) * 8 * HAS_;

        if (s + 1 < T_ && tid < 32) {
            int tn = dir ? (T_ - 2 - s) : (s + 1);
            int row = tid >> 2, seg = tid & 3;
            cp16(xS_base + (rb ^ 1) * XBUF + (unsigned)(row * XS_ + seg * 8) * 2,
                 g_xh + ((size_t)tn * B_ + b0 + row) * 32 + seg * 8);
            asm volatile("cp.async.commit_group;");
        }

        if (s > 0) {
            int tp = dir ? (T_ - s) : (s - 1);
            __half2 hv = *(__half2*)&hA[rb * 8 * HAS_ + yr * HAS_ + yc];
            *(__half2*)&g_y0h[((size_t)tp * B_ + b0 + yr) * (2 * H_) + dir * H_ + yc] = hv;
        }

        // split chains: a = bias + even ks, b = odd ks
        float c0a[4] = {bi, bi, bfv, bfv};
        float c1a[4] = {bg, bg, bo, bo};
        float c0b[4] = {0.f, 0.f, 0.f, 0.f};
        float c1b[4] = {0.f, 0.f, 0.f, 0.f};

        {
            unsigned r0, r1, r2, r3;
            asm volatile("ldmatrix.sync.aligned.m8n8.x4.shared.b16 {%0,%1,%2,%3}, [%4];"
                : "=r"(r0), "=r"(r1), "=r"(r2), "=r"(r3) : "r"(lx));
            asm volatile("mma.sync.aligned.m16n8k16.row.col.f32.f16.f16.f32 "
                "{%0,%1,%2,%3}, {%4,%5,%6,%7}, {%8,%9}, {%0,%1,%2,%3};"
                : "+f"(c0a[0]), "+f"(c0a[1]), "+f"(c0a[2]), "+f"(c0a[3])
                : "r"(Ax[0][0][0]), "r"(Ax[0][0][1]), "r"(Ax[0][0][2]), "r"(Ax[0][0][3]),
                  "r"(r0), "r"(r1));
            asm volatile("mma.sync.aligned.m16n8k16.row.col.f32.f16.f16.f32 "
                "{%0,%1,%2,%3}, {%4,%5,%6,%7}, {%8,%9}, {%0,%1,%2,%3};"
                : "+f"(c1a[0]), "+f"(c1a[1]), "+f"(c1a[2]), "+f"(c1a[3])
                : "r"(Ax[0][1][0]), "r"(Ax[0][1][1]), "r"(Ax[0][1][2]), "r"(Ax[0][1][3]),
                  "r"(r0), "r"(r1));
            asm volatile("mma.sync.aligned.m16n8k16.row.col.f32.f16.f16.f32 "
                "{%0,%1,%2,%3}, {%4,%5,%6,%7}, {%8,%9}, {%0,%1,%2,%3};"
                : "+f"(c0b[0]), "+f"(c0b[1]), "+f"(c0b[2]), "+f"(c0b[3])
                : "r"(Ax[1][0][0]), "r"(Ax[1][0][1]), "r"(Ax[1][0][2]), "r"(Ax[1][0][3]),
                  "r"(r2), "r"(r3));
            asm volatile("mma.sync.aligned.m16n8k16.row.col.f32.f16.f16.f32 "
                "{%0,%1,%2,%3}, {%4,%5,%6,%7}, {%8,%9}, {%0,%1,%2,%3};"
                : "+f"(c1b[0]), "+f"(c1b[1]), "+f"(c1b[2]), "+f"(c1b[3])
                : "r"(Ax[1][1][0]), "r"(Ax[1][1][1]), "r"(Ax[1][1][2]), "r"(Ax[1][1][3]),
                  "r"(r2), "r"(r3));
        }

        #pragma unroll
        for (int k2 = 0; k2 < 4; k2++) {
            unsigned r0, r1, r2, r3;
            asm volatile("ldmatrix.sync.aligned.m8n8.x4.shared.b16 {%0,%1,%2,%3}, [%4];"
                : "=r"(r0), "=r"(r1), "=r"(r2), "=r"(r3) : "r"(lm + k2 * 64));
            asm volatile("mma.sync.aligned.m16n8k16.row.col.f32.f16.f16.f32 "
                "{%0,%1,%2,%3}, {%4,%5,%6,%7}, {%8,%9}, {%0,%1,%2,%3};"
                : "+f"(c0a[0]), "+f"(c0a[1]), "+f"(c0a[2]), "+f"(c0a[3])
                : "r"(Af[2*k2][0][0]), "r"(Af[2*k2][0][1]), "r"(Af[2*k2][0][2]), "r"(Af[2*k2][0][3]),
                  "r"(r0), "r"(r1));
            asm volatile("mma.sync.aligned.m16n8k16.row.col.f32.f16.f16.f32 "
                "{%0,%1,%2,%3}, {%4,%5,%6,%7}, {%8,%9}, {%0,%1,%2,%3};"
                : "+f"(c1a[0]), "+f"(c1a[1]), "+f"(c1a[2]), "+f"(c1a[3])
                : "r"(Af[2*k2][1][0]), "r"(Af[2*k2][1][1]), "r"(Af[2*k2][1][2]), "r"(Af[2*k2][1][3]),
                  "r"(r0), "r"(r1));
            asm volatile("mma.sync.aligned.m16n8k16.row.col.f32.f16.f16.f32 "
                "{%0,%1,%2,%3}, {%4,%5,%6,%7}, {%8,%9}, {%0,%1,%2,%3};"
                : "+f"(c0b[0]), "+f"(c0b[1]), "+f"(c0b[2]), "+f"(c0b[3])
                : "r"(Af[2*k2+1][0][0]), "r"(Af[2*k2+1][0][1]), "r"(Af[2*k2+1][0][2]), "r"(Af[2*k2+1][0][3]),
                  "r"(r2), "r"(r3));
            asm volatile("mma.sync.aligned.m16n8k16.row.col.f32.f16.f16.f32 "
                "{%0,%1,%2,%3}, {%4,%5,%6,%7}, {%8,%9}, {%0,%1,%2,%3};"
                : "+f"(c1b[0]), "+f"(c1b[1]), "+f"(c1b[2]), "+f"(c1b[3])
                : "r"(Af[2*k2+1][1][0]), "r"(Af[2*k2+1][1][1]), "r"(Af[2*k2+1][1][2]), "r"(Af[2*k2+1][1][3]),
                  "r"(r2), "r"(r3));
        }

        float ii0 = fmaf(tanhap(c0a[0] + c0b[0]), 0.5f, 0.5f);
        float ii1 = fmaf(tanhap(c0a[1] + c0b[1]), 0.5f, 0.5f);
        float ff0 = fmaf(tanhap(c0a[2] + c0b[2]), 0.5f, 0.5f);
        float ff1 = fmaf(tanhap(c0a[3] + c0b[3]), 0.5f, 0.5f);
        float gg0 = tanhap(c1a[0] + c1b[0]);
        float gg1 = tanhap(c1a[1] + c1b[1]);
        float oo0 = fmaf(tanhap(c1a[2] + c1b[2]), 0.5f, 0.5f);
        float oo1 = fmaf(tanhap(c1a[3] + c1b[3]), 0.5f, 0.5f);

        cst0 = fmaf(ff0, cst0, ii0 * gg0);
        cst1 = fmaf(ff1, cst1, ii1 * gg1);
        h0v = oo0 * tanhap(cst0);
        h1v = oo1 * tanhap(cst1);

        hw[(2 * tg)     * HAS_ + hc] = __float2half(h0v);
        hw[(2 * tg + 1) * HAS_ + hc] = __float2half(h1v);

        if (s + 1 < T_ && tid < 32) {
            asm volatile("cp.async.wait_group 0;");
        }
        __syncthreads();
    }

    {
        int tp = dir ? 0 : (T_ - 1);
        __half2 hv = *(__half2*)&hA[0 * 8 * HAS_ + yr * HAS_ + yc];
        *(__half2*)&g_y0h[((size_t)tp * B_ + b0 + yr) * (2 * H_) + dir * H_ + yc] = hv;
    }

    const int d = dir;
    hn[((size_t)d * B_ + brow0) * H_ + hc] = h0v;
    hn[((size_t)d * B_ + brow1) * H_ + hc] = h1v;
    cn[((size_t)d * B_ + brow0) * H_ + hc] = cst0;
    cn[((size_t)d * B_ + brow1) * H_ + hc] = cst1;
}

// ---------------- layer-1 scan; split chains + deferred y1 ----------------
__global__ __launch_bounds__(512) void lstm_scan_mma(
    const float* __restrict__ whhf, const float* __restrict__ whhb,
    float* __restrict__ y1, float* __restrict__ hn, float* __restrict__ cn)
{
    __shared__ __half hA[2 * 8 * HAS_];
    __shared__ float  ybuf[2 * 8 * YBS_];

    const int tid  = threadIdx.x;
    const int lane = tid & 31;
    const int w    = tid >> 5;
    const int dir  = blockIdx.y;
    const int b0   = blockIdx.x * MB_;
    const int g4 = lane >> 2, tg = lane & 3;
    const float* __restrict__ whh = dir ? whhb : whhf;
    const float* __restrict__ gx  = g_gx[dir];

    unsigned Af[8][2][4];
    #pragma unroll
    for (int ks = 0; ks < 8; ks++)
        #pragma unroll
        for (int tl = 0; tl < 2; tl++) {
            const float* pA = whh + (size_t)((2 * tl)     * 128 + 8 * w + g4) * H_ + ks * 16 + tg * 2;
            const float* pB = whh + (size_t)((2 * tl + 1) * 128 + 8 * w + g4) * H_ + ks * 16 + tg * 2;
            float2 vA0 = *(const float2*)pA;
            float2 vB0 = *(const float2*)pB;
            float2 vA1 = *(const float2*)(pA + 8);
            float2 vB1 = *(const float2*)(pB + 8);
            __half2 h0 = __floats2half2_rn(vA0.x, vA0.y);
            __half2 h1 = __floats2half2_rn(vB0.x, vB0.y);
            __half2 h2 = __floats2half2_rn(vA1.x, vA1.y);
            __half2 h3 = __floats2half2_rn(vB1.x, vB1.y);
            Af[ks][tl][0] = *(unsigned*)&h0;
            Af[ks][tl][1] = *(unsigned*)&h1;
            Af[ks][tl][2] = *(unsigned*)&h2;
            Af[ks][tl][3] = *(unsigned*)&h3;
        }

    for (int p = tid; p < 2 * 8 * HAS_; p += 512) hA[p] = __float2half(0.f);

    const int hc    = 8 * w + g4;
    const int brow0 = b0 + 2 * tg;
    const int brow1 = brow0 + 1;
    float cst0 = 0.f, cst1 = 0.f;
    float h0 = 0.f, h1 = 0.f;

    const unsigned hA_base = (unsigned)__cvta_generic_to_shared(hA);
    const unsigned lmB4 = hA_base + (((lane & 7) * HAS_) + ((lane >> 3) & 3) * 8) * 2;
    const unsigned BUFB = 8 * HAS_ * 2;

    const int bg0 = b0 >> 3;
    const float* gxb = gx + 2 * tg;

    const int yr = tid >> 6;
    const int yc = (tid & 63) * 2;

    __syncthreads();

    float2 xi, xf, xg, xo;
    {
        int t0 = dir ? (T_ - 1) : 0;
        const float* p = gxb + ((size_t)t0 * 32 + bg0) * G_ * 8;
        xi = *(const float2*)(p + (0 * 128 + hc) * 8);
        xf = *(const float2*)(p + (1 * 128 + hc) * 8);
        xg = *(const float2*)(p + (2 * 128 + hc) * 8);
        xo = *(const float2*)(p + (3 * 128 + hc) * 8);
    }

    for (int s = 0; s < T_; s++) {
        const int rb = s & 1;
        const unsigned lm = lmB4 + rb * BUFB;
        __half* hw = hA + (rb ^ 1) * 8 * HAS_;
        float* yw = ybuf + (rb ^ 1) * 8 * YBS_;

        float2 ni, nf2, ng, no;
        if (s + 1 < T_) {
            int tn = dir ? (T_ - 2 - s) : (s + 1);
            const float* p = gxb + ((size_t)tn * 32 + bg0) * G_ * 8;
            ni  = *(const float2*)(p + (0 * 128 + hc) * 8);
            nf2 = *(const float2*)(p + (1 * 128 + hc) * 8);
            ng  = *(const float2*)(p + (2 * 128 + hc) * 8);
            no  = *(const float2*)(p + (3 * 128 + hc) * 8);
        } else {
            ni = nf2 = ng = no = make_float2(0.f, 0.f);
        }

        if (s > 0) {
            int tp = dir ? (T_ - s) : (s - 1);
            float2 hv = *(float2*)&ybuf[rb * 8 * YBS_ + yr * YBS_ + yc];
            *(float2*)&y1[((size_t)(b0 + yr) * T_ + tp) * (2 * H_) + dir * H_ + yc] = hv;
        }

        float c0a[4] = {0.f, 0.f, 0.f, 0.f};
        float c1a[4] = {0.f, 0.f, 0.f, 0.f};
        float c0b[4] = {0.f, 0.f, 0.f, 0.f};
        float c1b[4] = {0.f, 0.f, 0.f, 0.f};

        #pragma unroll
        for (int k2 = 0; k2 < 4; k2++) {
            unsigned r0, r1, r2, r3;
            asm volatile("ldmatrix.sync.aligned.m8n8.x4.shared.b16 {%0,%1,%2,%3}, [%4];"
                : "=r"(r0), "=r"(r1), "=r"(r2), "=r"(r3) : "r"(lm + k2 * 64));
            asm volatile("mma.sync.aligned.m16n8k16.row.col.f32.f16.f16.f32 "
                "{%0,%1,%2,%3}, {%4,%5,%6,%7}, {%8,%9}, {%0,%1,%2,%3};"
                : "+f"(c0a[0]), "+f"(c0a[1]), "+f"(c0a[2]), "+f"(c0a[3])
                : "r"(Af[2*k2][0][0]), "r"(Af[2*k2][0][1]), "r"(Af[2*k2][0][2]), "r"(Af[2*k2][0][3]),
                  "r"(r0), "r"(r1));
            asm volatile("mma.sync.aligned.m16n8k16.row.col.f32.f16.f16.f32 "
                "{%0,%1,%2,%3}, {%4,%5,%6,%7}, {%8,%9}, {%0,%1,%2,%3};"
                : "+f"(c1a[0]), "+f"(c1a[1]), "+f"(c1a[2]), "+f"(c1a[3])
                : "r"(Af[2*k2][1][0]), "r"(Af[2*k2][1][1]), "r"(Af[2*k2][1][2]), "r"(Af[2*k2][1][3]),
                  "r"(r0), "r"(r1));
            asm volatile("mma.sync.aligned.m16n8k16.row.col.f32.f16.f16.f32 "
                "{%0,%1,%2,%3}, {%4,%5,%6,%7}, {%8,%9}, {%0,%1,%2,%3};"
                : "+f"(c0b[0]), "+f"(c0b[1]), "+f"(c0b[2]), "+f"(c0b[3])
                : "r"(Af[2*k2+1][0][0]), "r"(Af[2*k2+1][0][1]), "r"(Af[2*k2+1][0][2]), "r"(Af[2*k2+1][0][3]),
                  "r"(r2), "r"(r3));
            asm volatile("mma.sync.aligned.m16n8k16.row.col.f32.f16.f16.f32 "
                "{%0,%1,%2,%3}, {%4,%5,%6,%7}, {%8,%9}, {%0,%1,%2,%3};"
                : "+f"(c1b[0]), "+f"(c1b[1]), "+f"(c1b[2]), "+f"(c1b[3])
                : "r"(Af[2*k2+1][1][0]), "r"(Af[2*k2+1][1][1]), "r"(Af[2*k2+1][1][2]), "r"(Af[2*k2+1][1][3]),
                  "r"(r2), "r"(r3));
        }

        float ii0 = fmaf(tanhap(fmaf(c0a[0] + c0b[0], 0.5f, xi.x)), 0.5f, 0.5f);
        float ii1 = fmaf(tanhap(fmaf(c0a[1] + c0b[1], 0.5f, xi.y)), 0.5f, 0.5f);
        float ff0 = fmaf(tanhap(fmaf(c0a[2] + c0b[2], 0.5f, xf.x)), 0.5f, 0.5f);
        float ff1 = fmaf(tanhap(fmaf(c0a[3] + c0b[3], 0.5f, xf.y)), 0.5f, 0.5f);
        float gg0 = tanhap(c1a[0] + c1b[0] + xg.x);
        float gg1 = tanhap(c1a[1] + c1b[1] + xg.y);
        float oo0 = fmaf(tanhap(fmaf(c1a[2] + c1b[2], 0.5f, xo.x)), 0.5f, 0.5f);
        float oo1 = fmaf(tanhap(fmaf(c1a[3] + c1b[3], 0.5f, xo.y)), 0.5f, 0.5f);

        cst0 = fmaf(ff0, cst0, ii0 * gg0);
        cst1 = fmaf(ff1, cst1, ii1 * gg1);
        h0 = oo0 * tanhap(cst0);
        h1 = oo1 * tanhap(cst1);

        hw[(2 * tg)     * HAS_ + hc] = __float2half(h0);
        hw[(2 * tg + 1) * HAS_ + hc] = __float2half(h1);
        yw[(2 * tg)     * YBS_ + hc] = h0;
        yw[(2 * tg + 1) * YBS_ + hc] = h1;

        xi = ni; xf = nf2; xg = ng; xo = no;
        __syncthreads();
    }

    {
        int tp = dir ? 0 : (T_ - 1);
        float2 hv = *(float2*)&ybuf[0 * 8 * YBS_ + yr * YBS_ + yc];
        *(float2*)&y1[((size_t)(b0 + yr) * T_ + tp) * (2 * H_) + dir * H_ + yc] = hv;
    }

    const int d = 2 + dir;
    hn[((size_t)d * B_ + brow0) * H_ + hc] = h0;
    hn[((size_t)d * B_ + brow1) * H_ + hc] = h1;
    cn[((size_t)d * B_ + brow0) * H_ + hc] = cst0;
    cn[((size_t)d * B_ + brow1) * H_ + hc] = cst1;
}

// ---------------- launch ----------------
extern "C" void kernel_launch(void* const* d_in, const int* in_sizes, int n_in,
                              void* d_out, int out_size) {
    const float* x     = (const float*)d_in[0];
    const float* wih0f = (const float*)d_in[1];
    const float* whh0f = (const float*)d_in[2];
    const float* b0f   = (const float*)d_in[3];
    const float* wih0b = (const float*)d_in[4];
    const float* whh0b = (const float*)d_in[5];
    const float* b0b   = (const float*)d_in[6];
    const float* wih1f = (const float*)d_in[7];
    const float* whh1f = (const float*)d_in[8];
    const float* b1f   = (const float*)d_in[9];
    const float* wih1b = (const float*)d_in[10];
    const float* whh1b = (const float*)d_in[11];
    const float* b1b   = (const float*)d_in[12];
    (void)in_sizes; (void)n_in; (void)out_size;

    float* out = (float*)d_out;
    float* y1 = out;
    float* hn = out + Y1SZ_;
    float* cn = hn + 4 * B_ * H_;

    cudaFuncSetAttribute(gemm_gx_kernel, cudaFuncAttributeMaxDynamicSharedMemorySize, GEMM_SMEM);

    // fp16 conversions
    conv_x_kernel<<<(BT_ * 32 + 255) / 256, 256>>>(x);
    conv_w1_kernel<<<(2 * G_ * 256 + 255) / 256, 256>>>(wih1f, wih1b);

    // layer 0: fused input-GEMM + scan
    lstm_scan_fused0<<<dim3(B_ / MB_, 2), 512>>>(wih0f, whh0f, b0f, wih0b, whh0b, b0b, hn, cn);

    // layer 1
    gemm_gx_kernel<<<dim3(8, BT_ / 128), 256, GEMM_SMEM>>>(b1f, b1b);
    lstm_scan_mma<<<dim3(B_ / MB_, 2), 512>>>(whh1f, whh1b, y1, hn, cn);
}